// round 14
// baseline (speedup 1.0000x reference)
#include <cuda_runtime.h>
#include <cuda_bf16.h>

// GroCo loss v7 — HMMA Gram, dependency-chain fix.
// v6 ran the K-quarter loop (p) INSIDE the row loop (n): 8 back-to-back
// accumulating HMMAs per acc[n] = exposed RAW chain (~3800 cyc/warp/tile).
// v7 swaps to p-outer / n-inner: 16 independent chains interleave, MMA
// latency fully hidden, tile becomes issue-bound. Everything else identical
// to the verified v6 (rel_err 1.4e-7).

#define BN 8192
#define DD 128
#define NTJ 64

__device__ float          g_n[2][BN * DD];
__device__ __nv_bfloat16  g_nb[2][BN * DD];
__device__ float          g_pos[BN];
__device__ double         g_acc;

// ---------------- helpers ----------------
__device__ __forceinline__ unsigned s2u(const void* p) {
    unsigned a;
    asm("{ .reg .u64 t; cvta.to.shared.u64 t, %1; cvt.u32.u64 %0, t; }"
        : "=r"(a) : "l"(p));
    return a;
}

// swizzled SMEM address for (row, 16B chunk) of a 128x128 bf16 tile:
// row stride 256B, chunk index XORed with row&7 -> ldmatrix conflict-free.
__device__ __forceinline__ unsigned sw_addr(unsigned base, int row, int chunk) {
    return base + (unsigned)(row << 8) + (unsigned)(((chunk ^ (row & 7)) << 4));
}

// cp.async one 128x128 bf16 tile (row-major global) into swizzled SMEM.
__device__ __forceinline__ void cpasync_tile(unsigned sb,
                                             const __nv_bfloat16* src, int tid) {
    const char* s = (const char*)src;
#pragma unroll
    for (int i = 0; i < 8; ++i) {            // 2048 chunks / 256 threads
        int c = tid + (i << 8);
        int row = c >> 4, chunk = c & 15;
        unsigned dst = sw_addr(sb, row, chunk);
        asm volatile("cp.async.cg.shared.global [%0], [%1], 16;"
                     :: "r"(dst), "l"(s + c * 16) : "memory");
    }
}

// Branchless insert into ascending top-10 (t[0] = smallest kept).
__device__ __forceinline__ void topk_insert10(float (&t)[10], float v) {
#pragma unroll
    for (int k = 0; k < 9; ++k) t[k] = fminf(fmaxf(v, t[k]), t[k + 1]);
    t[9] = fmaxf(v, t[9]);
}

// per-row finalize: soft odd-even sort (steepness=1) + BCE term sum.
__device__ __forceinline__ float row_loss(const float (&tt)[10], float pos) {
    float s[11];
#pragma unroll
    for (int k = 0; k < 10; ++k) s[k] = tt[k];
    s[10] = pos;

    const float INV_PI = 0.3183098861837907f;
    float alpha[55];
#pragma unroll
    for (int layer = 0; layer < 11; ++layer) {
        int off = layer & 1;
#pragma unroll
        for (int pi = 0; pi < 5; ++pi) {
            int ia = off + 2 * pi, ib = ia + 1;
            float av = s[ia], bv = s[ib];
            float al = atanf(bv - av) * INV_PI + 0.5f;
            alpha[layer * 5 + pi] = al;
            s[ia] = al * av + (1.0f - al) * bv;
            s[ib] = (1.0f - al) * av + al * bv;
        }
    }
    float wp[11], wn[11];
#pragma unroll
    for (int k = 0; k < 11; ++k) { wp[k] = 0.0f; wn[k] = 1.0f; }
    wp[10] = 1.0f; wn[10] = 0.0f;
#pragma unroll
    for (int layer = 10; layer >= 0; --layer) {
        int off = layer & 1;
#pragma unroll
        for (int pi = 0; pi < 5; ++pi) {
            int ia = off + 2 * pi, ib = ia + 1;
            float al = alpha[layer * 5 + pi];
            float pa = wp[ia], pb = wp[ib];
            wp[ia] = al * pa + (1.0f - al) * pb;
            wp[ib] = (1.0f - al) * pa + al * pb;
            float na = wn[ia], nb2 = wn[ib];
            wn[ia] = al * na + (1.0f - al) * nb2;
            wn[ib] = (1.0f - al) * na + al * nb2;
        }
    }
    float local = 0.0f;
#pragma unroll
    for (int i = 0; i < 11; ++i) {
        float ppos = fminf(fmaxf(wp[i], 0.0f), 1.0f);
        float pneg = fminf(fmaxf(wn[i], 0.0f), 1.0f);
        float tp = (i == 10) ? fmaxf(logf(ppos),        -100.0f)
                             : fmaxf(logf(1.0f - ppos), -100.0f);
        float tn = (i < 10)  ? fmaxf(logf(pneg),        -100.0f)
                             : fmaxf(logf(1.0f - pneg), -100.0f);
        local += tp + tn;
    }
    return local;
}

// ---------------- kernels ----------------
__global__ void zero_kernel() { g_acc = 0.0; }

__global__ void normalize_kernel(const float* __restrict__ x, int dir) {
    int gw   = (blockIdx.x * blockDim.x + threadIdx.x) >> 5;  // warp per row
    int lane = threadIdx.x & 31;
    if (gw >= BN) return;
    float4 v = reinterpret_cast<const float4*>(x)[gw * (DD / 4) + lane];
    float s = v.x * v.x + v.y * v.y + v.z * v.z + v.w * v.w;
#pragma unroll
    for (int o = 16; o > 0; o >>= 1) s += __shfl_xor_sync(0xffffffffu, s, o);
    float inv = 1.0f / fmaxf(sqrtf(s), 1e-8f);
    float4 o4 = make_float4(v.x * inv, v.y * inv, v.z * inv, v.w * inv);
    reinterpret_cast<float4*>(g_n[dir])[gw * (DD / 4) + lane] = o4;
    __nv_bfloat162 lo = __floats2bfloat162_rn(o4.x, o4.y);
    __nv_bfloat162 hi = __floats2bfloat162_rn(o4.z, o4.w);
    uint2 pk;
    pk.x = *reinterpret_cast<unsigned*>(&lo);
    pk.y = *reinterpret_cast<unsigned*>(&hi);
    reinterpret_cast<uint2*>(g_nb[dir])[gw * 32 + lane] = pk;
}

__global__ void pos_kernel() {
    int gw   = (blockIdx.x * blockDim.x + threadIdx.x) >> 5;
    int lane = threadIdx.x & 31;
    if (gw >= BN) return;
    float4 a = reinterpret_cast<const float4*>(g_n[0])[gw * (DD / 4) + lane];
    float4 b = reinterpret_cast<const float4*>(g_n[1])[gw * (DD / 4) + lane];
    float s = a.x * b.x + a.y * b.y + a.z * b.z + a.w * b.w;
#pragma unroll
    for (int o = 16; o > 0; o >>= 1) s += __shfl_xor_sync(0xffffffffu, s, o);
    if (lane == 0) g_pos[gw] = s;
}

// SMEM: A @0 (32KB), B0 @32768, B1 @65536, sred @98304 (2KB)
#define SMEM_DYN (98304 + 2048)

__global__ void __launch_bounds__(256, 1) gram_kernel() {
    extern __shared__ char smem[];
    unsigned sbase = s2u(smem);
    double* sred = (double*)(smem + 98304);
    int tid = threadIdx.x, w = tid >> 5, l = tid & 31;
    int dir = blockIdx.x >> 6, it = blockIdx.x & 63;
    const __nv_bfloat16* nb = g_nb[dir];

    // prologue: A tile + B tile 0
    cpasync_tile(sbase, nb + (size_t)it * 128 * DD, tid);
    cpasync_tile(sbase + 32768, nb, tid);
    asm volatile("cp.async.commit_group;" ::: "memory");
    asm volatile("cp.async.wait_group 0;" ::: "memory");
    __syncthreads();

    // A fragments: 8 k-atoms, resident. m16n8k16 A-frag via ldmatrix.x4:
    // groups g0..g3 -> (m+0,k0),(m+8,k0),(m+0,k8),(m+8,k8)
    unsigned af[8][4];
    {
        int g = l >> 3, ri = l & 7;
        int arow = w * 16 + ((g & 1) << 3) + ri;
        int cadd = g >> 1;
#pragma unroll
        for (int ka = 0; ka < 8; ++ka) {
            unsigned ad = sw_addr(sbase, arow, ka * 2 + cadd);
            asm volatile(
                "ldmatrix.sync.aligned.m8n8.x4.shared.b16 {%0,%1,%2,%3}, [%4];"
                : "=r"(af[ka][0]), "=r"(af[ka][1]), "=r"(af[ka][2]), "=r"(af[ka][3])
                : "r"(ad));
        }
    }

    float t0[10], t1[10];
#pragma unroll
    for (int k = 0; k < 10; ++k) { t0[k] = -1e30f; t1[k] = -1e30f; }
    int r0 = it * 128 + w * 16 + (l >> 2);
    int r1 = r0 + 8;
    int brow = l & 7;         // b-frag row-in-atom
    int bchunk = l >> 3;      // 0..3: (ka lo/hi) x (k half)
    int cbase = (l & 3) << 1; // col offset within n-atom for c-frag

#pragma unroll 1
    for (int jt = 0; jt < NTJ; ++jt) {
        unsigned bs = sbase + 32768 + (unsigned)((jt & 1) << 15);
        if (jt + 1 < NTJ) {  // prefetch next B into the other buffer
            cpasync_tile(sbase + 32768 + (unsigned)(((jt + 1) & 1) << 15),
                         nb + (size_t)(jt + 1) * 128 * DD, tid);
            asm volatile("cp.async.commit_group;" ::: "memory");
        }

        // p OUTER, n INNER: 16 independent accumulation chains interleave,
        // HMMA latency hidden (v6 had p inner -> exposed 8-deep RAW chain).
        float acc[16][4];
#pragma unroll
        for (int p = 0; p < 4; ++p) {
#pragma unroll
            for (int n = 0; n < 16; ++n) {
                unsigned b0, b1, b2, b3;
                unsigned bd = sw_addr(bs, (n << 3) + brow, (p << 2) + bchunk);
                asm volatile(
                    "ldmatrix.sync.aligned.m8n8.x4.shared.b16 {%0,%1,%2,%3}, [%4];"
                    : "=r"(b0), "=r"(b1), "=r"(b2), "=r"(b3) : "r"(bd));
                if (p == 0) {
                    asm volatile(
                        "mma.sync.aligned.m16n8k16.row.col.f32.bf16.bf16.f32 "
                        "{%0,%1,%2,%3}, {%4,%5,%6,%7}, {%8,%9}, {%10,%10,%10,%10};"
                        : "=f"(acc[n][0]), "=f"(acc[n][1]),
                          "=f"(acc[n][2]), "=f"(acc[n][3])
                        : "r"(af[0][0]), "r"(af[0][1]), "r"(af[0][2]), "r"(af[0][3]),
                          "r"(b0), "r"(b1), "f"(0.0f));
                } else {
                    asm volatile(
                        "mma.sync.aligned.m16n8k16.row.col.f32.bf16.bf16.f32 "
                        "{%0,%1,%2,%3}, {%4,%5,%6,%7}, {%8,%9}, {%0,%1,%2,%3};"
                        : "+f"(acc[n][0]), "+f"(acc[n][1]),
                          "+f"(acc[n][2]), "+f"(acc[n][3])
                        : "r"(af[2 * p][0]), "r"(af[2 * p][1]),
                          "r"(af[2 * p][2]), "r"(af[2 * p][3]),
                          "r"(b0), "r"(b1));
                }
                asm volatile(
                    "mma.sync.aligned.m16n8k16.row.col.f32.bf16.bf16.f32 "
                    "{%0,%1,%2,%3}, {%4,%5,%6,%7}, {%8,%9}, {%0,%1,%2,%3};"
                    : "+f"(acc[n][0]), "+f"(acc[n][1]),
                      "+f"(acc[n][2]), "+f"(acc[n][3])
                    : "r"(af[2 * p + 1][0]), "r"(af[2 * p + 1][1]),
                      "r"(af[2 * p + 1][2]), "r"(af[2 * p + 1][3]),
                      "r"(b2), "r"(b3));
            }
        }

        // fold this tile's sims into per-lane top-10 (2 rows x 32 cols)
        int jb = jt * 128 + cbase;
#pragma unroll
        for (int n = 0; n < 16; ++n) {
            int j0 = jb + (n << 3), j1 = j0 + 1;
            float v;
            v = acc[n][0]; if (v > t0[0] && j0 != r0) topk_insert10(t0, v);
            v = acc[n][1]; if (v > t0[0] && j1 != r0) topk_insert10(t0, v);
            v = acc[n][2]; if (v > t1[0] && j0 != r1) topk_insert10(t1, v);
            v = acc[n][3]; if (v > t1[0] && j1 != r1) topk_insert10(t1, v);
        }

        if (jt + 1 < NTJ)
            asm volatile("cp.async.wait_group 0;" ::: "memory");
        __syncthreads();
    }

    // quad butterfly merge (lanes 4q..4q+3 share rows). Snapshot before each
    // exchange: partners' live arrays mutate mid-step, snapshots don't.
#pragma unroll
    for (int step = 1; step <= 2; step <<= 1) {
        float s0[10], s1[10];
#pragma unroll
        for (int k = 0; k < 10; ++k) { s0[k] = t0[k]; s1[k] = t1[k]; }
#pragma unroll
        for (int k = 0; k < 10; ++k) {
            float v0 = __shfl_xor_sync(0xffffffffu, s0[k], step);
            float v1 = __shfl_xor_sync(0xffffffffu, s1[k], step);
            if (v0 > t0[0]) topk_insert10(t0, v0);
            if (v1 > t1[0]) topk_insert10(t1, v1);
        }
    }

    float local = 0.0f;
    if ((l & 3) == 0) {
        local  = row_loss(t0, g_pos[r0]);
        local += row_loss(t1, g_pos[r1]);
    }
    sred[tid] = (double)local;
    __syncthreads();
#pragma unroll
    for (int st = 128; st > 0; st >>= 1) {
        if (tid < st) sred[tid] += sred[tid + st];
        __syncthreads();
    }
    if (tid == 0) atomicAdd(&g_acc, sred[0]);
}

__global__ void writeout_kernel(float* __restrict__ out) {
    out[0] = (float)(-g_acc / (4.0 * 11.0 * (double)BN));
}

extern "C" void kernel_launch(void* const* d_in, const int* in_sizes, int n_in,
                              void* d_out, int out_size) {
    const float* aug1 = (const float*)d_in[0];
    const float* aug2 = (const float*)d_in[1];
    float* out = (float*)d_out;

    cudaFuncSetAttribute(gram_kernel,
                         cudaFuncAttributeMaxDynamicSharedMemorySize, SMEM_DYN);

    zero_kernel<<<1, 1>>>();
    normalize_kernel<<<(BN * 32) / 256, 256>>>(aug1, 0);
    normalize_kernel<<<(BN * 32) / 256, 256>>>(aug2, 1);
    pos_kernel<<<(BN * 32) / 256, 256>>>();
    gram_kernel<<<128, 256, SMEM_DYN>>>();
    writeout_kernel<<<1, 1>>>(out);
}